// round 13
// baseline (speedup 1.0000x reference)
#include <cuda_runtime.h>

#define HID   50
#define SEQT  512
#define WPB   8            // warps (= batch elements) per block
#define BLOCK 256
#define RPAD  32           // padded h pairs per row (64 floats)

typedef unsigned long long ull;

// packed 2xfp32 FMA: d = a*b + c
__device__ __forceinline__ ull fma2(ull a, ull b, ull c) {
    ull d;
    asm("fma.rn.f32x2 %0, %1, %2, %3;" : "=l"(d) : "l"(a), "l"(b), "l"(c));
    return d;
}
__device__ __forceinline__ float hsum2(ull v) {
    float lo, hi;
    asm("mov.b64 {%0, %1}, %2;" : "=f"(lo), "=f"(hi) : "l"(v));
    return lo + hi;
}
__device__ __forceinline__ ull pack2(float lo, float hi) {
    ull v;
    asm("mov.b64 %0, {%1, %2};" : "=l"(v) : "f"(lo), "f"(hi));
    return v;
}
__device__ __forceinline__ float tanhapx(float x) {
    float y;
    asm("tanh.approx.f32 %0, %1;" : "=f"(y) : "f"(x));
    return y;
}
__device__ __forceinline__ float sigapx(float x) {
    return __fmaf_rn(0.5f, tanhapx(0.5f * x), 0.5f);
}

__global__ void __launch_bounds__(BLOCK, 1)
lstm_fused_kernel(const float* __restrict__ x,
                  const float* __restrict__ W_ih,
                  const float* __restrict__ W_hh,
                  const float* __restrict__ b_ih,
                  const float* __restrict__ b_hh,
                  const float* __restrict__ W_out,
                  const float* __restrict__ b_out,
                  float* __restrict__ out,
                  int B)
{
    // per-warp double-buffered h, stored as packed f32 pairs
    __shared__ __align__(16) ull   sh_h[2][WPB][RPAD];
    __shared__ __align__(16) float sh_wi[64][4];   // per-unit W_ih (rows >=50 zero)
    __shared__ __align__(16) float sh_bs[64][4];   // per-unit gate biases

    const int tid  = threadIdx.x;
    const int w    = tid >> 5;          // warp = element slot
    const int lane = tid & 31;
    const int u0   = 2 * lane;          // this lane's first hidden unit
    const int uc   = (u0 < HID) ? u0 : (HID - 2);   // clamp for fake lanes

    const int  b   = blockIdx.x * WPB + w;
    const bool act = (b < B);
    const int  bb  = act ? b : 0;

    // ---- one-time init ----
    for (int i = tid; i < 2 * WPB * RPAD; i += BLOCK)
        (&sh_h[0][0][0])[i] = 0ull;
    if (tid < 64) {
        #pragma unroll
        for (int g = 0; g < 4; g++) {
            float wi = 0.0f, bv = 0.0f;
            if (tid < HID) {
                const int row = g * HID + tid;     // gate order: i, f, g, o
                wi = W_ih[row];
                bv = b_ih[row] + b_hh[row];
            }
            sh_wi[tid][g] = wi;
            sh_bs[tid][g] = bv;
        }
    }

    // W_hh rows for this lane's 2 units x 4 gates, as f32 pairs: 200 regs
    ull w2[2][4][25];
    #pragma unroll
    for (int uu = 0; uu < 2; uu++) {
        #pragma unroll
        for (int g = 0; g < 4; g++) {
            const ull* wrow =
                reinterpret_cast<const ull*>(W_hh + (g * HID + uc + uu) * HID);
            #pragma unroll
            for (int p = 0; p < 25; p++)
                w2[uu][g][p] = wrow[p];
        }
    }

    // output weights for this lane's units (0 on fake lanes -> no predication)
    const float wo0 = (u0 < HID) ? W_out[u0]     : 0.0f;
    const float wo1 = (u0 < HID) ? W_out[u0 + 1] : 0.0f;
    const float bout = b_out[0];

    const float* __restrict__ xrow = x   + (size_t)bb * SEQT;
    float*       __restrict__ orow = out + (size_t)bb * SEQT;

    float c0 = 0.0f, c1 = 0.0f;
    int cur = 0;

    __syncthreads();    // init visible (once)

    for (int t = 0; t < SEQT; t++) {
        const int nxt = cur ^ 1;
        const float xt = xrow[t];

        // dot: 8 independent chains (2 units x 4 gates) over 25 h-pairs
        const ull* hrow = &sh_h[cur][w][0];
        ull a00=0ull,a01=0ull,a02=0ull,a03=0ull;
        ull a10=0ull,a11=0ull,a12=0ull,a13=0ull;
        #pragma unroll
        for (int p = 0; p < 25; p++) {
            const ull hv = hrow[p];      // LDS.64, warp-broadcast
            a00 = fma2(hv, w2[0][0][p], a00);
            a01 = fma2(hv, w2[0][1][p], a01);
            a02 = fma2(hv, w2[0][2][p], a02);
            a03 = fma2(hv, w2[0][3][p], a03);
            a10 = fma2(hv, w2[1][0][p], a10);
            a11 = fma2(hv, w2[1][1][p], a11);
            a12 = fma2(hv, w2[1][2][p], a12);
            a13 = fma2(hv, w2[1][3][p], a13);
        }

        const float4 wi0 = *reinterpret_cast<const float4*>(&sh_wi[u0][0]);
        const float4 bs0 = *reinterpret_cast<const float4*>(&sh_bs[u0][0]);
        const float4 wi1 = *reinterpret_cast<const float4*>(&sh_wi[u0 + 1][0]);
        const float4 bs1 = *reinterpret_cast<const float4*>(&sh_bs[u0 + 1][0]);

        // unit 0 cell update
        float hn0;
        {
            const float g0 = hsum2(a00) + __fmaf_rn(xt, wi0.x, bs0.x);
            const float g1 = hsum2(a01) + __fmaf_rn(xt, wi0.y, bs0.y);
            const float g2 = hsum2(a02) + __fmaf_rn(xt, wi0.z, bs0.z);
            const float g3 = hsum2(a03) + __fmaf_rn(xt, wi0.w, bs0.w);
            const float ig = sigapx(g0), fg = sigapx(g1);
            const float gg = tanhapx(g2), og = sigapx(g3);
            c0 = __fmaf_rn(fg, c0, ig * gg);
            hn0 = og * tanhapx(c0);
        }
        // unit 1 cell update
        float hn1;
        {
            const float g0 = hsum2(a10) + __fmaf_rn(xt, wi1.x, bs1.x);
            const float g1 = hsum2(a11) + __fmaf_rn(xt, wi1.y, bs1.y);
            const float g2 = hsum2(a12) + __fmaf_rn(xt, wi1.z, bs1.z);
            const float g3 = hsum2(a13) + __fmaf_rn(xt, wi1.w, bs1.w);
            const float ig = sigapx(g0), fg = sigapx(g1);
            const float gg = tanhapx(g2), og = sigapx(g3);
            c1 = __fmaf_rn(fg, c1, ig * gg);
            hn1 = og * tanhapx(c1);
        }

        // publish h pair (fake lanes write padding pairs 25..31, never read)
        sh_h[nxt][w][lane] = pack2(hn0, hn1);
        __syncwarp();

        // output projection: register-only butterfly (wo=0 on fake lanes)
        float yc = __fmaf_rn(hn0, wo0, hn1 * wo1);
        #pragma unroll
        for (int off = 16; off > 0; off >>= 1)
            yc += __shfl_xor_sync(0xffffffffu, yc, off);
        if (act && lane == 0)
            orow[t] = yc + bout;

        cur = nxt;
    }
}

extern "C" void kernel_launch(void* const* d_in, const int* in_sizes, int n_in,
                              void* d_out, int out_size)
{
    const float* x     = (const float*)d_in[0];
    const float* W_ih  = (const float*)d_in[1];
    const float* W_hh  = (const float*)d_in[2];
    const float* b_ih  = (const float*)d_in[3];
    const float* b_hh  = (const float*)d_in[4];
    const float* W_out = (const float*)d_in[5];
    const float* b_out = (const float*)d_in[6];
    float* out = (float*)d_out;

    const int B = in_sizes[0] / SEQT;          // I == 1, x is [B, T, 1]
    const int grid = (B + WPB - 1) / WPB;
    lstm_fused_kernel<<<grid, BLOCK>>>(x, W_ih, W_hh, b_ih, b_hh, W_out, b_out, out, B);
}

// round 14
// speedup vs baseline: 2.2771x; 2.2771x over previous
#include <cuda_runtime.h>

#define HID   50
#define SEQT  512
#define NGRP  2            // independent 64-thread groups per block
#define NB    4            // batch elements per block (2 per group)
#define BLOCK 128          // 4 warps
#define ROWP  52           // padded h row (floats)

// packed 2xfp32 FMA: d = a*b + c
__device__ __forceinline__ unsigned long long fma2(unsigned long long a,
                                                   unsigned long long b,
                                                   unsigned long long c) {
    unsigned long long d;
    asm("fma.rn.f32x2 %0, %1, %2, %3;" : "=l"(d) : "l"(a), "l"(b), "l"(c));
    return d;
}
__device__ __forceinline__ float hsum2(unsigned long long v) {
    float lo, hi;
    asm("mov.b64 {%0, %1}, %2;" : "=f"(lo), "=f"(hi) : "l"(v));
    return lo + hi;
}
__device__ __forceinline__ float tanhapx(float x) {
    float y;
    asm("tanh.approx.f32 %0, %1;" : "=f"(y) : "f"(x));
    return y;
}
__device__ __forceinline__ float sigapx(float x) {
    return __fmaf_rn(0.5f, tanhapx(0.5f * x), 0.5f);
}
// named barrier over one 64-thread group (2 warps)
__device__ __forceinline__ void group_bar(int id) {
    asm volatile("bar.sync %0, 64;" :: "r"(id) : "memory");
}

__global__ void __launch_bounds__(BLOCK, 1)
lstm_fused_kernel(const float* __restrict__ x,
                  const float* __restrict__ W_ih,
                  const float* __restrict__ W_hh,
                  const float* __restrict__ b_ih,
                  const float* __restrict__ b_hh,
                  const float* __restrict__ W_out,
                  const float* __restrict__ b_out,
                  float* __restrict__ out,
                  int B)
{
    // per-group double-buffered h (2 elems each)
    __shared__ __align__(16) float sh_h[NGRP][2][2][ROWP];
    __shared__ __align__(16) float sh_wout[ROWP];
    __shared__ __align__(16) float sh_bs[HID][4];   // per-unit gate biases
    __shared__ __align__(16) float sh_wi[HID][4];   // per-unit W_ih

    const int tid = threadIdx.x;
    const int g   = tid >> 6;            // group 0..1 (warps {0,1} / {2,3})
    const int r   = tid & 63;            // lane within group

    // straggler balancing: on 'flipped' placements the 14 non-gate lanes sit
    // in the group's FIRST warp instead of its second, so co-resident blocks
    // (bid, bid+148: bit2 differs) put their out-lane warps on different SMSPs.
    const int flip  = (blockIdx.x >> 2) & 1;
    const int shift = flip ? 14 : 0;
    const int j     = r - shift;               // hidden unit if 0 <= j < 50
    const bool gate_lane = (j >= 0) && (j < HID);
    const int jj = gate_lane ? j : 0;           // clamped for addressing

    const int bA = blockIdx.x * NB + g * 2;     // this group's stream A elem
    const int bB = bA + 1;
    const bool actA = (bA < B);
    const bool actB = (bB < B);

    // out lanes: first two non-gate lanes handle elems A,B
    const int  os       = flip ? r : (r - HID);
    const bool out_lane = (!gate_lane) && (os >= 0) && (os < 2) && (bA + os < B);

    // ---- one-time init (block-wide) ----
    for (int i = tid; i < NGRP * 2 * 2 * ROWP; i += BLOCK)
        (&sh_h[0][0][0][0])[i] = 0.0f;
    if (tid < ROWP)
        sh_wout[tid] = (tid < HID) ? W_out[tid] : 0.0f;
    if (tid < HID) {
        #pragma unroll
        for (int gg = 0; gg < 4; gg++) {
            const int row = gg * HID + tid;
            sh_bs[tid][gg] = b_ih[row] + b_hh[row];
            sh_wi[tid][gg] = W_ih[row];
        }
    }

    // 4 W_hh gate rows for unit j, f32 pairs (shared by both streams): 200 regs
    unsigned long long w2[4][25];
    if (gate_lane) {
        #pragma unroll
        for (int gg = 0; gg < 4; gg++) {
            const int row = gg * HID + jj;  // PyTorch gate order: i, f, g, o
            const unsigned long long* wrow =
                reinterpret_cast<const unsigned long long*>(W_hh + row * HID);
            #pragma unroll
            for (int p = 0; p < 25; p++)
                w2[gg][p] = wrow[p];
        }
    }
    const float bout = b_out[0];

    const float* __restrict__ xrowA = x + (size_t)(actA ? bA : 0) * SEQT;
    const float* __restrict__ xrowB = x + (size_t)(actB ? bB : 0) * SEQT;
    float* __restrict__ orow = out + (size_t)(out_lane ? (bA + os) : 0) * SEQT;

    float cA = 0.0f, cB = 0.0f;
    float xA = xrowA[0], xB = xrowB[0];   // prefetched x_t
    int cur = 0;

    __syncthreads();           // init visible to both groups (once)

    const int barid = g + 1;   // named barrier ids 1..2

    for (int t = 0; t < SEQT; t++) {
        const int nxt = cur ^ 1;

        if (gate_lane) {
            // prefetch next x (off the critical path)
            const int tn = (t + 1 < SEQT) ? (t + 1) : t;
            const float xAn = xrowA[tn];
            const float xBn = xrowB[tn];

            const float* hA = &sh_h[g][cur][0][0];   // elem B row at +ROWP
            unsigned long long a0=0ull,a1=0ull,a2=0ull,a3=0ull;
            unsigned long long e0=0ull,e1=0ull,e2=0ull,e3=0ull;

            #pragma unroll
            for (int q = 0; q < 12; q++) {
                const ulonglong2 hvA = *reinterpret_cast<const ulonglong2*>(hA + q * 4);
                const ulonglong2 hvB = *reinterpret_cast<const ulonglong2*>(hA + ROWP + q * 4);
                a0 = fma2(hvA.x, w2[0][2*q],   a0);
                e0 = fma2(hvB.x, w2[0][2*q],   e0);
                a1 = fma2(hvA.x, w2[1][2*q],   a1);
                e1 = fma2(hvB.x, w2[1][2*q],   e1);
                a2 = fma2(hvA.x, w2[2][2*q],   a2);
                e2 = fma2(hvB.x, w2[2][2*q],   e2);
                a3 = fma2(hvA.x, w2[3][2*q],   a3);
                e3 = fma2(hvB.x, w2[3][2*q],   e3);
                a0 = fma2(hvA.y, w2[0][2*q+1], a0);
                e0 = fma2(hvB.y, w2[0][2*q+1], e0);
                a1 = fma2(hvA.y, w2[1][2*q+1], a1);
                e1 = fma2(hvB.y, w2[1][2*q+1], e1);
                a2 = fma2(hvA.y, w2[2][2*q+1], a2);
                e2 = fma2(hvB.y, w2[2][2*q+1], e2);
                a3 = fma2(hvA.y, w2[3][2*q+1], a3);
                e3 = fma2(hvB.y, w2[3][2*q+1], e3);
            }
            {
                const unsigned long long hvA =
                    *reinterpret_cast<const unsigned long long*>(hA + 48);
                const unsigned long long hvB =
                    *reinterpret_cast<const unsigned long long*>(hA + ROWP + 48);
                a0 = fma2(hvA, w2[0][24], a0);
                e0 = fma2(hvB, w2[0][24], e0);
                a1 = fma2(hvA, w2[1][24], a1);
                e1 = fma2(hvB, w2[1][24], e1);
                a2 = fma2(hvA, w2[2][24], a2);
                e2 = fma2(hvB, w2[2][24], e2);
                a3 = fma2(hvA, w2[3][24], a3);
                e3 = fma2(hvB, w2[3][24], e3);
            }

            // tail operands (loaded after the dot's LDS stream)
            const float4 bsv = *reinterpret_cast<const float4*>(&sh_bs[jj][0]);
            const float4 wiv = *reinterpret_cast<const float4*>(&sh_wi[jj][0]);

            // stream A cell update
            {
                const float g0 = hsum2(a0) + __fmaf_rn(xA, wiv.x, bsv.x);
                const float g1 = hsum2(a1) + __fmaf_rn(xA, wiv.y, bsv.y);
                const float g2 = hsum2(a2) + __fmaf_rn(xA, wiv.z, bsv.z);
                const float g3 = hsum2(a3) + __fmaf_rn(xA, wiv.w, bsv.w);
                const float ig = sigapx(g0), fg = sigapx(g1);
                const float gg = tanhapx(g2), og = sigapx(g3);
                cA = __fmaf_rn(fg, cA, ig * gg);
                if (actA) sh_h[g][nxt][0][jj] = og * tanhapx(cA);
            }
            // stream B cell update
            {
                const float g0 = hsum2(e0) + __fmaf_rn(xB, wiv.x, bsv.x);
                const float g1 = hsum2(e1) + __fmaf_rn(xB, wiv.y, bsv.y);
                const float g2 = hsum2(e2) + __fmaf_rn(xB, wiv.z, bsv.z);
                const float g3 = hsum2(e3) + __fmaf_rn(xB, wiv.w, bsv.w);
                const float ig = sigapx(g0), fg = sigapx(g1);
                const float gg = tanhapx(g2), og = sigapx(g3);
                cB = __fmaf_rn(fg, cB, ig * gg);
                if (actB) sh_h[g][nxt][1][jj] = og * tanhapx(cB);
            }

            xA = xAn;
            xB = xBn;
        } else if (out_lane && t > 0) {
            // out[t-1] from the READ buffer, concurrent with gate compute
            const float* hp = &sh_h[g][cur][os][0];
            float y0 = bout, y1 = 0.0f, y2 = 0.0f, y3 = 0.0f;
            #pragma unroll
            for (int kq = 0; kq < 13; kq++) {       // pads are zero in both
                const float4 hv = *reinterpret_cast<const float4*>(hp + kq * 4);
                const float4 wv = *reinterpret_cast<const float4*>(sh_wout + kq * 4);
                y0 = __fmaf_rn(hv.x, wv.x, y0);
                y1 = __fmaf_rn(hv.y, wv.y, y1);
                y2 = __fmaf_rn(hv.z, wv.z, y2);
                y3 = __fmaf_rn(hv.w, wv.w, y3);
            }
            orow[t - 1] = (y0 + y1) + (y2 + y3);
        }

        group_bar(barid);      // only this group's 2 warps
        cur = nxt;
    }

    // tail: out[T-1] from the final h buffer
    if (out_lane) {
        const float* hp = &sh_h[g][cur][os][0];
        float y0 = bout, y1 = 0.0f, y2 = 0.0f, y3 = 0.0f;
        #pragma unroll
        for (int kq = 0; kq < 13; kq++) {
            const float4 hv = *reinterpret_cast<const float4*>(hp + kq * 4);
            const float4 wv = *reinterpret_cast<const float4*>(sh_wout + kq * 4);
            y0 = __fmaf_rn(hv.x, wv.x, y0);
            y1 = __fmaf_rn(hv.y, wv.y, y1);
            y2 = __fmaf_rn(hv.z, wv.z, y2);
            y3 = __fmaf_rn(hv.w, wv.w, y3);
        }
        orow[SEQT - 1] = (y0 + y1) + (y2 + y3);
    }
}

extern "C" void kernel_launch(void* const* d_in, const int* in_sizes, int n_in,
                              void* d_out, int out_size)
{
    const float* x     = (const float*)d_in[0];
    const float* W_ih  = (const float*)d_in[1];
    const float* W_hh  = (const float*)d_in[2];
    const float* b_ih  = (const float*)d_in[3];
    const float* b_hh  = (const float*)d_in[4];
    const float* W_out = (const float*)d_in[5];
    const float* b_out = (const float*)d_in[6];
    float* out = (float*)d_out;

    const int B = in_sizes[0] / SEQT;          // I == 1, x is [B, T, 1]
    const int grid = (B + NB - 1) / NB;
    lstm_fused_kernel<<<grid, BLOCK>>>(x, W_ih, W_hh, b_ih, b_hh, W_out, b_out, out, B);
}

// round 15
// speedup vs baseline: 2.4405x; 1.0717x over previous
#include <cuda_runtime.h>

#define HID   50
#define SEQT  512
#define NSTR  4            // batch elements (streams) per block
#define BLOCK 128          // 100 gate lanes + 4 out lanes + 24 idle
#define ROWP  52           // padded h row (floats)

typedef unsigned long long ull;

// packed 2xfp32 FMA: d = a*b + c
__device__ __forceinline__ ull fma2(ull a, ull b, ull c) {
    ull d;
    asm("fma.rn.f32x2 %0, %1, %2, %3;" : "=l"(d) : "l"(a), "l"(b), "l"(c));
    return d;
}
__device__ __forceinline__ float hsum2(ull v) {
    float lo, hi;
    asm("mov.b64 {%0, %1}, %2;" : "=f"(lo), "=f"(hi) : "l"(v));
    return lo + hi;
}
__device__ __forceinline__ float tanhapx(float x) {
    float y;
    asm("tanh.approx.f32 %0, %1;" : "=f"(y) : "f"(x));
    return y;
}
__device__ __forceinline__ float sigapx(float x) {
    return __fmaf_rn(0.5f, tanhapx(0.5f * x), 0.5f);
}

__global__ void __launch_bounds__(BLOCK, 3)
lstm_fused_kernel(const float* __restrict__ x,
                  const float* __restrict__ W_ih,
                  const float* __restrict__ W_hh,
                  const float* __restrict__ b_ih,
                  const float* __restrict__ b_hh,
                  const float* __restrict__ W_out,
                  const float* __restrict__ b_out,
                  float* __restrict__ out,
                  int B)
{
    // double-buffered h for the block's 4 streams
    __shared__ __align__(16) float  sh_h[2][NSTR][ROWP];
    __shared__ __align__(16) float  sh_wout[ROWP];
    __shared__ __align__(8)  float2 sh_wi[HID][2];   // [j][gp] = W_ih of gates 2gp,2gp+1
    __shared__ __align__(8)  float2 sh_bs[HID][2];   // [j][gp] = biases of gates 2gp,2gp+1

    const int tid = threadIdx.x;
    const int j   = tid >> 1;            // hidden unit (gate lanes)
    const int gp  = tid & 1;             // 0 -> gates {i,f}; 1 -> gates {g,o}
    const bool gate_lane = (tid < 2 * HID);
    const int jj = gate_lane ? j : 0;

    const int bA = blockIdx.x * NSTR;    // first stream elem (bA < B by grid)

    // out lanes 100..103 -> streams 0..3
    const int  os       = tid - 2 * HID;
    const bool out_lane = (!gate_lane) && (os < NSTR) && (bA + os < B);

    // per-stream activity + clamped x/out row offsets
    const bool act0 = (bA + 0 < B), act1 = (bA + 1 < B);
    const bool act2 = (bA + 2 < B), act3 = (bA + 3 < B);
    const int xo0 = 0;
    const int xo1 = act1 ? SEQT     : 0;
    const int xo2 = act2 ? 2 * SEQT : 0;
    const int xo3 = act3 ? 3 * SEQT : 0;

    // ---- one-time init ----
    for (int i = tid; i < 2 * NSTR * ROWP; i += BLOCK)
        (&sh_h[0][0][0])[i] = 0.0f;
    if (tid < ROWP)
        sh_wout[tid] = (tid < HID) ? W_out[tid] : 0.0f;
    if (tid < HID) {
        #pragma unroll
        for (int p = 0; p < 2; p++) {
            const int r0 = (2 * p) * HID + tid, r1 = (2 * p + 1) * HID + tid;
            sh_wi[tid][p] = make_float2(W_ih[r0], W_ih[r1]);
            sh_bs[tid][p] = make_float2(b_ih[r0] + b_hh[r0], b_ih[r1] + b_hh[r1]);
        }
    }

    // W_hh rows for this thread's 2 gates, f32 pairs (shared by 4 streams): 100 regs
    ull w2[2][25];
    if (gate_lane) {
        #pragma unroll
        for (int gg = 0; gg < 2; gg++) {
            const int row = (2 * gp + gg) * HID + jj;   // gate order: i, f, g, o
            const ull* wrow = reinterpret_cast<const ull*>(W_hh + row * HID);
            #pragma unroll
            for (int p = 0; p < 25; p++)
                w2[gg][p] = wrow[p];
        }
    }
    const float bout = b_out[0];

    const float* __restrict__ xbase = x   + (size_t)bA * SEQT;
    float*       __restrict__ obase = out + (size_t)bA * SEQT;

    float c0 = 0.0f, c1 = 0.0f;   // cells of this lane's 2 owned streams
    int cur = 0;

    __syncthreads();

    for (int t = 0; t < SEQT; t++) {
        const int nxt = cur ^ 1;

        if (gate_lane) {
            const float x0 = xbase[xo0 + t];
            const float x1 = xbase[xo1 + t];
            const float x2 = xbase[xo2 + t];
            const float x3 = xbase[xo3 + t];
            const float2 wiv = sh_wi[jj][gp];
            const float2 bsv = sh_bs[jj][gp];

            const float* hb = &sh_h[cur][0][0];
            ull a00=0ull,a01=0ull;   // stream 0, gates (2gp, 2gp+1)
            ull a10=0ull,a11=0ull;   // stream 1
            ull a20=0ull,a21=0ull;   // stream 2
            ull a30=0ull,a31=0ull;   // stream 3

            #pragma unroll
            for (int q = 0; q < 12; q++) {
                const ulonglong2 h0 = *reinterpret_cast<const ulonglong2*>(hb + 0*ROWP + q*4);
                const ulonglong2 h1 = *reinterpret_cast<const ulonglong2*>(hb + 1*ROWP + q*4);
                const ulonglong2 h2 = *reinterpret_cast<const ulonglong2*>(hb + 2*ROWP + q*4);
                const ulonglong2 h3 = *reinterpret_cast<const ulonglong2*>(hb + 3*ROWP + q*4);
                a00 = fma2(h0.x, w2[0][2*q],   a00);
                a10 = fma2(h1.x, w2[0][2*q],   a10);
                a20 = fma2(h2.x, w2[0][2*q],   a20);
                a30 = fma2(h3.x, w2[0][2*q],   a30);
                a01 = fma2(h0.x, w2[1][2*q],   a01);
                a11 = fma2(h1.x, w2[1][2*q],   a11);
                a21 = fma2(h2.x, w2[1][2*q],   a21);
                a31 = fma2(h3.x, w2[1][2*q],   a31);
                a00 = fma2(h0.y, w2[0][2*q+1], a00);
                a10 = fma2(h1.y, w2[0][2*q+1], a10);
                a20 = fma2(h2.y, w2[0][2*q+1], a20);
                a30 = fma2(h3.y, w2[0][2*q+1], a30);
                a01 = fma2(h0.y, w2[1][2*q+1], a01);
                a11 = fma2(h1.y, w2[1][2*q+1], a11);
                a21 = fma2(h2.y, w2[1][2*q+1], a21);
                a31 = fma2(h3.y, w2[1][2*q+1], a31);
            }
            {
                const ull h0 = *reinterpret_cast<const ull*>(hb + 0*ROWP + 48);
                const ull h1 = *reinterpret_cast<const ull*>(hb + 1*ROWP + 48);
                const ull h2 = *reinterpret_cast<const ull*>(hb + 2*ROWP + 48);
                const ull h3 = *reinterpret_cast<const ull*>(hb + 3*ROWP + 48);
                a00 = fma2(h0, w2[0][24], a00);
                a10 = fma2(h1, w2[0][24], a10);
                a20 = fma2(h2, w2[0][24], a20);
                a30 = fma2(h3, w2[0][24], a30);
                a01 = fma2(h0, w2[1][24], a01);
                a11 = fma2(h1, w2[1][24], a11);
                a21 = fma2(h2, w2[1][24], a21);
                a31 = fma2(h3, w2[1][24], a31);
            }

            // pre-activations; v0 = first gate (i or g), v1 = second (f or o)
            const float p00 = hsum2(a00) + __fmaf_rn(x0, wiv.x, bsv.x);
            const float p01 = hsum2(a01) + __fmaf_rn(x0, wiv.y, bsv.y);
            const float p10 = hsum2(a10) + __fmaf_rn(x1, wiv.x, bsv.x);
            const float p11 = hsum2(a11) + __fmaf_rn(x1, wiv.y, bsv.y);
            const float p20 = hsum2(a20) + __fmaf_rn(x2, wiv.x, bsv.x);
            const float p21 = hsum2(a21) + __fmaf_rn(x2, wiv.y, bsv.y);
            const float p30 = hsum2(a30) + __fmaf_rn(x3, wiv.x, bsv.x);
            const float p31 = hsum2(a31) + __fmaf_rn(x3, wiv.y, bsv.y);

            const float v00 = gp ? tanhapx(p00) : sigapx(p00);  // i or g
            const float v01 = gp ? tanhapx(p10) : sigapx(p10);
            const float v02 = gp ? tanhapx(p20) : sigapx(p20);
            const float v03 = gp ? tanhapx(p30) : sigapx(p30);
            const float v10 = sigapx(p01);                      // f or o
            const float v11 = sigapx(p11);
            const float v12 = sigapx(p21);
            const float v13 = sigapx(p31);

            // exchange: gp0 owns streams 0,1 (sends s2,s3 gates);
            //           gp1 owns streams 2,3 (sends s0,s1 gates)
            const unsigned m = __activemask();
            const float r0 = __shfl_xor_sync(m, gp ? v00 : v02, 1);
            const float r1 = __shfl_xor_sync(m, gp ? v10 : v12, 1);
            const float r2 = __shfl_xor_sync(m, gp ? v01 : v03, 1);
            const float r3 = __shfl_xor_sync(m, gp ? v11 : v13, 1);

            // owned stream #1 (s0 for gp0, s2 for gp1)
            {
                const float ig = gp ? r0  : v00;
                const float fg = gp ? r1  : v10;
                const float gg = gp ? v02 : r0;
                const float og = gp ? v12 : r1;
                c0 = __fmaf_rn(fg, c0, ig * gg);
                const float hn = og * tanhapx(c0);
                const bool acts = gp ? act2 : act0;
                float* dst = &sh_h[nxt][gp ? 2 : 0][jj];
                if (acts) *dst = hn;
            }
            // owned stream #2 (s1 for gp0, s3 for gp1)
            {
                const float ig = gp ? r2  : v01;
                const float fg = gp ? r3  : v11;
                const float gg = gp ? v03 : r2;
                const float og = gp ? v13 : r3;
                c1 = __fmaf_rn(fg, c1, ig * gg);
                const float hn = og * tanhapx(c1);
                const bool acts = gp ? act3 : act1;
                float* dst = &sh_h[nxt][gp ? 3 : 1][jj];
                if (acts) *dst = hn;
            }
        } else if (out_lane && t > 0) {
            // out[t-1] for stream os, from the READ buffer (concurrent)
            const float* hp = &sh_h[cur][os][0];
            float y0 = bout, y1 = 0.0f, y2 = 0.0f, y3 = 0.0f;
            #pragma unroll
            for (int kq = 0; kq < 13; kq++) {       // pads are zero in both
                const float4 hv = *reinterpret_cast<const float4*>(hp + kq * 4);
                const float4 wv = *reinterpret_cast<const float4*>(sh_wout + kq * 4);
                y0 = __fmaf_rn(hv.x, wv.x, y0);
                y1 = __fmaf_rn(hv.y, wv.y, y1);
                y2 = __fmaf_rn(hv.z, wv.z, y2);
                y3 = __fmaf_rn(hv.w, wv.w, y3);
            }
            obase[(size_t)os * SEQT + (t - 1)] = (y0 + y1) + (y2 + y3);
        }

        __syncthreads();
        cur = nxt;
    }

    // tail: out[T-1]
    if (out_lane) {
        const float* hp = &sh_h[cur][os][0];
        float y0 = bout, y1 = 0.0f, y2 = 0.0f, y3 = 0.0f;
        #pragma unroll
        for (int kq = 0; kq < 13; kq++) {
            const float4 hv = *reinterpret_cast<const float4*>(hp + kq * 4);
            const float4 wv = *reinterpret_cast<const float4*>(sh_wout + kq * 4);
            y0 = __fmaf_rn(hv.x, wv.x, y0);
            y1 = __fmaf_rn(hv.y, wv.y, y1);
            y2 = __fmaf_rn(hv.z, wv.z, y2);
            y3 = __fmaf_rn(hv.w, wv.w, y3);
        }
        obase[(size_t)os * SEQT + (SEQT - 1)] = (y0 + y1) + (y2 + y3);
    }
}

extern "C" void kernel_launch(void* const* d_in, const int* in_sizes, int n_in,
                              void* d_out, int out_size)
{
    const float* x     = (const float*)d_in[0];
    const float* W_ih  = (const float*)d_in[1];
    const float* W_hh  = (const float*)d_in[2];
    const float* b_ih  = (const float*)d_in[3];
    const float* b_hh  = (const float*)d_in[4];
    const float* W_out = (const float*)d_in[5];
    const float* b_out = (const float*)d_in[6];
    float* out = (float*)d_out;

    const int B = in_sizes[0] / SEQT;          // I == 1, x is [B, T, 1]
    const int grid = (B + NSTR - 1) / NSTR;
    lstm_fused_kernel<<<grid, BLOCK>>>(x, W_ih, W_hh, b_ih, b_hh, W_out, b_out, out, B);
}

// round 16
// speedup vs baseline: 2.5697x; 1.0529x over previous
#include <cuda_runtime.h>

#define HID   50
#define SEQT  512
#define NGRP  2            // independent 64-thread groups per block
#define NB    4            // batch elements per block (2 per group)
#define BLOCK 128          // 4 warps
#define ROWP  52           // padded h row (floats)

typedef unsigned long long ull;

// packed 2xfp32 FMA: d = a*b + c
__device__ __forceinline__ ull fma2(ull a, ull b, ull c) {
    ull d;
    asm("fma.rn.f32x2 %0, %1, %2, %3;" : "=l"(d) : "l"(a), "l"(b), "l"(c));
    return d;
}
__device__ __forceinline__ float hsum2(ull v) {
    float lo, hi;
    asm("mov.b64 {%0, %1}, %2;" : "=f"(lo), "=f"(hi) : "l"(v));
    return lo + hi;
}
__device__ __forceinline__ ull pack2(float lo, float hi) {
    ull v;
    asm("mov.b64 %0, {%1, %2};" : "=l"(v) : "f"(lo), "f"(hi));
    return v;
}
__device__ __forceinline__ float tanhapx(float x) {
    float y;
    asm("tanh.approx.f32 %0, %1;" : "=f"(y) : "f"(x));
    return y;
}
// named barrier over one 64-thread group (2 warps)
__device__ __forceinline__ void group_bar(int id) {
    asm volatile("bar.sync %0, 64;" :: "r"(id) : "memory");
}

__global__ void __launch_bounds__(BLOCK, 1)
lstm_fused_kernel(const float* __restrict__ x,
                  const float* __restrict__ W_ih,
                  const float* __restrict__ W_hh,
                  const float* __restrict__ b_ih,
                  const float* __restrict__ b_hh,
                  const float* __restrict__ W_out,
                  const float* __restrict__ b_out,
                  float* __restrict__ out,
                  int B)
{
    // per-group double-buffered h (2 elems each)
    __shared__ __align__(16) float sh_h[NGRP][2][2][ROWP];
    __shared__ __align__(16) float sh_wout[ROWP];
    __shared__ __align__(16) float sh_bs[HID][4];   // prescaled gate biases
    __shared__ __align__(16) float sh_wi[HID][4];   // prescaled W_ih

    const int tid = threadIdx.x;
    const int g   = tid >> 6;            // group 0..1
    const int r   = tid & 63;            // lane within group
    const int j   = r;                   // hidden unit (gate lanes < 50)
    const bool gate_lane = (r < HID);
    const int jj = gate_lane ? j : 0;

    const int bA = blockIdx.x * NB + g * 2;     // this group's stream A elem
    const int bB = bA + 1;
    const bool actA = (bA < B);
    const bool actB = (bB < B);

    // out lanes 50,51 of each group -> elems A,B
    const int  os       = r - HID;
    const bool out_lane = (!gate_lane) && (os < 2) && (bA + os < B);

    // ---- one-time init (block-wide) ----
    for (int i = tid; i < NGRP * 2 * 2 * ROWP; i += BLOCK)
        (&sh_h[0][0][0][0])[i] = 0.0f;
    if (tid < ROWP)
        sh_wout[tid] = (tid < HID) ? W_out[tid] : 0.0f;
    if (tid < HID) {
        #pragma unroll
        for (int gg = 0; gg < 4; gg++) {
            const float sc = (gg == 2) ? 1.0f : 0.5f;   // sigmoid gates prescaled
            const int row = gg * HID + tid;
            sh_bs[tid][gg] = (b_ih[row] + b_hh[row]) * sc;
            sh_wi[tid][gg] = W_ih[row] * sc;
        }
    }

    // 4 W_hh gate rows for unit j, f32 pairs; i/f/o rows prescaled by 0.5
    ull w2[4][25];
    if (gate_lane) {
        #pragma unroll
        for (int gg = 0; gg < 4; gg++) {
            const float sc = (gg == 2) ? 1.0f : 0.5f;
            const int row = gg * HID + jj;  // PyTorch gate order: i, f, g, o
            const float2* wrow =
                reinterpret_cast<const float2*>(W_hh + row * HID);
            #pragma unroll
            for (int p = 0; p < 25; p++) {
                const float2 wf = wrow[p];
                w2[gg][p] = pack2(wf.x * sc, wf.y * sc);
            }
        }
    }
    const float bout = b_out[0];

    const float* __restrict__ xrowA = x + (size_t)(actA ? bA : 0) * SEQT;
    const float* __restrict__ xrowB = x + (size_t)(actB ? bB : 0) * SEQT;
    float* __restrict__ orow = out + (size_t)(out_lane ? (bA + os) : 0) * SEQT;

    float cA = 0.0f, cB = 0.0f;
    int cur = 0;

    __syncthreads();           // init visible to both groups (once)

    const int barid = g + 1;   // named barrier ids 1..2

    for (int t = 0; t < SEQT; t++) {
        const int nxt = cur ^ 1;

        if (gate_lane) {
            // operands loaded at top of step: latency hides under the dot
            const float xA = xrowA[t];
            const float xB = xrowB[t];
            const float4 bsv = *reinterpret_cast<const float4*>(&sh_bs[jj][0]);
            const float4 wiv = *reinterpret_cast<const float4*>(&sh_wi[jj][0]);

            // accumulators initialized with the x-projection + bias (lo lane)
            ull a0 = pack2(__fmaf_rn(xA, wiv.x, bsv.x), 0.0f);
            ull a1 = pack2(__fmaf_rn(xA, wiv.y, bsv.y), 0.0f);
            ull a2 = pack2(__fmaf_rn(xA, wiv.z, bsv.z), 0.0f);
            ull a3 = pack2(__fmaf_rn(xA, wiv.w, bsv.w), 0.0f);
            ull e0 = pack2(__fmaf_rn(xB, wiv.x, bsv.x), 0.0f);
            ull e1 = pack2(__fmaf_rn(xB, wiv.y, bsv.y), 0.0f);
            ull e2 = pack2(__fmaf_rn(xB, wiv.z, bsv.z), 0.0f);
            ull e3 = pack2(__fmaf_rn(xB, wiv.w, bsv.w), 0.0f);

            const float* hAp = &sh_h[g][cur][0][0];   // elem B row at +ROWP
            const ulonglong2* pA = reinterpret_cast<const ulonglong2*>(hAp);
            const ulonglong2* pB = reinterpret_cast<const ulonglong2*>(hAp + ROWP);

            // software-pipelined dot: prefetch quad q+1 while fma-ing quad q
            ulonglong2 hvA = pA[0], hvB = pB[0];
            #pragma unroll
            for (int q = 0; q < 12; q++) {
                ulonglong2 hvAn, hvBn;
                if (q < 11) { hvAn = pA[q + 1]; hvBn = pB[q + 1]; }
                a0 = fma2(hvA.x, w2[0][2*q],   a0);
                a1 = fma2(hvA.x, w2[1][2*q],   a1);
                a2 = fma2(hvA.x, w2[2][2*q],   a2);
                a3 = fma2(hvA.x, w2[3][2*q],   a3);
                e0 = fma2(hvB.x, w2[0][2*q],   e0);
                e1 = fma2(hvB.x, w2[1][2*q],   e1);
                e2 = fma2(hvB.x, w2[2][2*q],   e2);
                e3 = fma2(hvB.x, w2[3][2*q],   e3);
                a0 = fma2(hvA.y, w2[0][2*q+1], a0);
                a1 = fma2(hvA.y, w2[1][2*q+1], a1);
                a2 = fma2(hvA.y, w2[2][2*q+1], a2);
                a3 = fma2(hvA.y, w2[3][2*q+1], a3);
                e0 = fma2(hvB.y, w2[0][2*q+1], e0);
                e1 = fma2(hvB.y, w2[1][2*q+1], e1);
                e2 = fma2(hvB.y, w2[2][2*q+1], e2);
                e3 = fma2(hvB.y, w2[3][2*q+1], e3);
                if (q < 11) { hvA = hvAn; hvB = hvBn; }
            }
            {   // h[48..49]
                const ull hA48 = *reinterpret_cast<const ull*>(hAp + 48);
                const ull hB48 = *reinterpret_cast<const ull*>(hAp + ROWP + 48);
                a0 = fma2(hA48, w2[0][24], a0);
                a1 = fma2(hA48, w2[1][24], a1);
                a2 = fma2(hA48, w2[2][24], a2);
                a3 = fma2(hA48, w2[3][24], a3);
                e0 = fma2(hB48, w2[0][24], e0);
                e1 = fma2(hB48, w2[1][24], e1);
                e2 = fma2(hB48, w2[2][24], e2);
                e3 = fma2(hB48, w2[3][24], e3);
            }

            // pre-activations (i/f/o already include the 0.5 prescale)
            const float pA0 = hsum2(a0), pA1 = hsum2(a1);
            const float pA2 = hsum2(a2), pA3 = hsum2(a3);
            const float pB0 = hsum2(e0), pB1 = hsum2(e1);
            const float pB2 = hsum2(e2), pB3 = hsum2(e3);

            // 8 independent MUFUs back-to-back
            const float tA0 = tanhapx(pA0), tA1 = tanhapx(pA1);
            const float tA2 = tanhapx(pA2), tA3 = tanhapx(pA3);
            const float tB0 = tanhapx(pB0), tB1 = tanhapx(pB1);
            const float tB2 = tanhapx(pB2), tB3 = tanhapx(pB3);

            // sig(p) = 0.5*tanh(p/2)+0.5, with p/2 already accumulated
            const float iA = __fmaf_rn(0.5f, tA0, 0.5f);
            const float fA = __fmaf_rn(0.5f, tA1, 0.5f);
            const float oA = __fmaf_rn(0.5f, tA3, 0.5f);
            const float iB = __fmaf_rn(0.5f, tB0, 0.5f);
            const float fB = __fmaf_rn(0.5f, tB1, 0.5f);
            const float oB = __fmaf_rn(0.5f, tB3, 0.5f);

            cA = __fmaf_rn(fA, cA, iA * tA2);
            cB = __fmaf_rn(fB, cB, iB * tB2);
            const float hcA = tanhapx(cA);
            const float hcB = tanhapx(cB);
            if (actA) sh_h[g][nxt][0][jj] = oA * hcA;
            if (actB) sh_h[g][nxt][1][jj] = oB * hcB;
        } else if (out_lane && t > 0) {
            // out[t-1] from the READ buffer, concurrent with gate compute
            const float* hp = &sh_h[g][cur][os][0];
            float y0 = bout, y1 = 0.0f, y2 = 0.0f, y3 = 0.0f;
            #pragma unroll
            for (int kq = 0; kq < 13; kq++) {       // pads are zero in both
                const float4 hv = *reinterpret_cast<const float4*>(hp + kq * 4);
                const float4 wv = *reinterpret_cast<const float4*>(sh_wout + kq * 4);
                y0 = __fmaf_rn(hv.x, wv.x, y0);
                y1 = __fmaf_rn(hv.y, wv.y, y1);
                y2 = __fmaf_rn(hv.z, wv.z, y2);
                y3 = __fmaf_rn(hv.w, wv.w, y3);
            }
            orow[t - 1] = (y0 + y1) + (y2 + y3);
        }

        group_bar(barid);      // only this group's 2 warps
        cur = nxt;
    }

    // tail: out[T-1] from the final h buffer
    if (out_lane) {
        const float* hp = &sh_h[g][cur][os][0];
        float y0 = bout, y1 = 0.0f, y2 = 0.0f, y3 = 0.0f;
        #pragma unroll
        for (int kq = 0; kq < 13; kq++) {
            const float4 hv = *reinterpret_cast<const float4*>(hp + kq * 4);
            const float4 wv = *reinterpret_cast<const float4*>(sh_wout + kq * 4);
            y0 = __fmaf_rn(hv.x, wv.x, y0);
            y1 = __fmaf_rn(hv.y, wv.y, y1);
            y2 = __fmaf_rn(hv.z, wv.z, y2);
            y3 = __fmaf_rn(hv.w, wv.w, y3);
        }
        orow[SEQT - 1] = (y0 + y1) + (y2 + y3);
    }
}

extern "C" void kernel_launch(void* const* d_in, const int* in_sizes, int n_in,
                              void* d_out, int out_size)
{
    const float* x     = (const float*)d_in[0];
    const float* W_ih  = (const float*)d_in[1];
    const float* W_hh  = (const float*)d_in[2];
    const float* b_ih  = (const float*)d_in[3];
    const float* b_hh  = (const float*)d_in[4];
    const float* W_out = (const float*)d_in[5];
    const float* b_out = (const float*)d_in[6];
    float* out = (float*)d_out;

    const int B = in_sizes[0] / SEQT;          // I == 1, x is [B, T, 1]
    const int grid = (B + NB - 1) / NB;
    lstm_fused_kernel<<<grid, BLOCK>>>(x, W_ih, W_hh, b_ih, b_hh, W_out, b_out, out, B);
}

// round 17
// speedup vs baseline: 2.5708x; 1.0004x over previous
#include <cuda_runtime.h>

#define HID   50
#define SEQT  512
#define NGRP  2            // independent 64-thread groups per block
#define NB    4            // batch elements per block (2 per group)
#define BLOCK 128          // 4 warps
#define ROWP  52           // padded h row (floats)

typedef unsigned long long ull;

// packed 2xfp32 FMA: d = a*b + c
__device__ __forceinline__ ull fma2(ull a, ull b, ull c) {
    ull d;
    asm("fma.rn.f32x2 %0, %1, %2, %3;" : "=l"(d) : "l"(a), "l"(b), "l"(c));
    return d;
}
__device__ __forceinline__ float hsum2(ull v) {
    float lo, hi;
    asm("mov.b64 {%0, %1}, %2;" : "=f"(lo), "=f"(hi) : "l"(v));
    return lo + hi;
}
__device__ __forceinline__ ull pack2(float lo, float hi) {
    ull v;
    asm("mov.b64 %0, {%1, %2};" : "=l"(v) : "f"(lo), "f"(hi));
    return v;
}
__device__ __forceinline__ float tanhapx(float x) {
    float y;
    asm("tanh.approx.f32 %0, %1;" : "=f"(y) : "f"(x));
    return y;
}
// named barrier over one 64-thread group (2 warps)
__device__ __forceinline__ void group_bar(int id) {
    asm volatile("bar.sync %0, 64;" :: "r"(id) : "memory");
}

__global__ void __launch_bounds__(BLOCK, 1)
lstm_fused_kernel(const float* __restrict__ x,
                  const float* __restrict__ W_ih,
                  const float* __restrict__ W_hh,
                  const float* __restrict__ b_ih,
                  const float* __restrict__ b_hh,
                  const float* __restrict__ W_out,
                  const float* __restrict__ b_out,
                  float* __restrict__ out,
                  int B)
{
    // per-group double-buffered h (2 elems each)
    __shared__ __align__(16) float sh_h[NGRP][2][2][ROWP];
    __shared__ __align__(16) float sh_wout[ROWP];
    __shared__ __align__(16) float sh_bs[HID][4];   // prescaled gate biases
    __shared__ __align__(16) float sh_wi[HID][4];   // prescaled W_ih

    const int tid = threadIdx.x;
    const int g   = tid >> 6;            // group 0..1
    const int r   = tid & 63;            // lane within group
    const int j   = r;                   // hidden unit (gate lanes < 50)
    const bool gate_lane = (r < HID);
    const int jj = gate_lane ? j : 0;

    const int bA = blockIdx.x * NB + g * 2;     // this group's stream A elem
    const int bB = bA + 1;
    const bool actA = (bA < B);
    const bool actB = (bB < B);

    // out lanes 50,51 of each group -> elems A,B
    const int  os       = r - HID;
    const bool out_lane = (!gate_lane) && (os < 2) && (bA + os < B);

    // ---- one-time init (block-wide) ----
    for (int i = tid; i < NGRP * 2 * 2 * ROWP; i += BLOCK)
        (&sh_h[0][0][0][0])[i] = 0.0f;
    if (tid < ROWP)
        sh_wout[tid] = (tid < HID) ? W_out[tid] : 0.0f;
    if (tid < HID) {
        #pragma unroll
        for (int gg = 0; gg < 4; gg++) {
            const float sc = (gg == 2) ? 1.0f : 0.5f;   // sigmoid gates prescaled
            const int row = gg * HID + tid;
            sh_bs[tid][gg] = (b_ih[row] + b_hh[row]) * sc;
            sh_wi[tid][gg] = W_ih[row] * sc;
        }
    }

    // 4 W_hh gate rows for unit j, f32 pairs; i/f/o rows prescaled by 0.5
    ull w2[4][25];
    if (gate_lane) {
        #pragma unroll
        for (int gg = 0; gg < 4; gg++) {
            const float sc = (gg == 2) ? 1.0f : 0.5f;
            const int row = gg * HID + jj;  // PyTorch gate order: i, f, g, o
            const float2* wrow =
                reinterpret_cast<const float2*>(W_hh + row * HID);
            #pragma unroll
            for (int p = 0; p < 25; p++) {
                const float2 wf = wrow[p];
                w2[gg][p] = pack2(wf.x * sc, wf.y * sc);
            }
        }
    }
    const float bout = b_out[0];

    const float* __restrict__ xrowA = x + (size_t)(actA ? bA : 0) * SEQT;
    const float* __restrict__ xrowB = x + (size_t)(actB ? bB : 0) * SEQT;
    float* __restrict__ orow = out + (size_t)(out_lane ? (bA + os) : 0) * SEQT;

    float cA = 0.0f, cB = 0.0f;
    int cur = 0;

    __syncthreads();           // init visible to both groups (once)

    const int barid = g + 1;   // named barrier ids 1..2

    for (int t = 0; t < SEQT; t++) {
        const int nxt = cur ^ 1;

        if (gate_lane) {
            // operands loaded at top of step: latency hides under the dot
            const float xA = xrowA[t];
            const float xB = xrowB[t];
            const float4 bsv = *reinterpret_cast<const float4*>(&sh_bs[jj][0]);
            const float4 wiv = *reinterpret_cast<const float4*>(&sh_wi[jj][0]);

            // accumulators initialized with the x-projection + bias (lo lane)
            ull a0 = pack2(__fmaf_rn(xA, wiv.x, bsv.x), 0.0f);
            ull a1 = pack2(__fmaf_rn(xA, wiv.y, bsv.y), 0.0f);
            ull a2 = pack2(__fmaf_rn(xA, wiv.z, bsv.z), 0.0f);
            ull a3 = pack2(__fmaf_rn(xA, wiv.w, bsv.w), 0.0f);
            ull e0 = pack2(__fmaf_rn(xB, wiv.x, bsv.x), 0.0f);
            ull e1 = pack2(__fmaf_rn(xB, wiv.y, bsv.y), 0.0f);
            ull e2 = pack2(__fmaf_rn(xB, wiv.z, bsv.z), 0.0f);
            ull e3 = pack2(__fmaf_rn(xB, wiv.w, bsv.w), 0.0f);

            const float* hAp = &sh_h[g][cur][0][0];   // elem B row at +ROWP
            const ulonglong2* pA = reinterpret_cast<const ulonglong2*>(hAp);
            const ulonglong2* pB = reinterpret_cast<const ulonglong2*>(hAp + ROWP);

            // software-pipelined dot: prefetch quad q+1 while fma-ing quad q
            ulonglong2 hvA = pA[0], hvB = pB[0];
            #pragma unroll
            for (int q = 0; q < 12; q++) {
                ulonglong2 hvAn, hvBn;
                if (q < 11) { hvAn = pA[q + 1]; hvBn = pB[q + 1]; }
                a0 = fma2(hvA.x, w2[0][2*q],   a0);
                a1 = fma2(hvA.x, w2[1][2*q],   a1);
                a2 = fma2(hvA.x, w2[2][2*q],   a2);
                a3 = fma2(hvA.x, w2[3][2*q],   a3);
                e0 = fma2(hvB.x, w2[0][2*q],   e0);
                e1 = fma2(hvB.x, w2[1][2*q],   e1);
                e2 = fma2(hvB.x, w2[2][2*q],   e2);
                e3 = fma2(hvB.x, w2[3][2*q],   e3);
                a0 = fma2(hvA.y, w2[0][2*q+1], a0);
                a1 = fma2(hvA.y, w2[1][2*q+1], a1);
                a2 = fma2(hvA.y, w2[2][2*q+1], a2);
                a3 = fma2(hvA.y, w2[3][2*q+1], a3);
                e0 = fma2(hvB.y, w2[0][2*q+1], e0);
                e1 = fma2(hvB.y, w2[1][2*q+1], e1);
                e2 = fma2(hvB.y, w2[2][2*q+1], e2);
                e3 = fma2(hvB.y, w2[3][2*q+1], e3);
                if (q < 11) { hvA = hvAn; hvB = hvBn; }
            }
            {   // h[48..49]
                const ull hA48 = *reinterpret_cast<const ull*>(hAp + 48);
                const ull hB48 = *reinterpret_cast<const ull*>(hAp + ROWP + 48);
                a0 = fma2(hA48, w2[0][24], a0);
                a1 = fma2(hA48, w2[1][24], a1);
                a2 = fma2(hA48, w2[2][24], a2);
                a3 = fma2(hA48, w2[3][24], a3);
                e0 = fma2(hB48, w2[0][24], e0);
                e1 = fma2(hB48, w2[1][24], e1);
                e2 = fma2(hB48, w2[2][24], e2);
                e3 = fma2(hB48, w2[3][24], e3);
            }

            // pre-activations (i/f/o already include the 0.5 prescale)
            const float pA0 = hsum2(a0), pA1 = hsum2(a1);
            const float pA2 = hsum2(a2), pA3 = hsum2(a3);
            const float pB0 = hsum2(e0), pB1 = hsum2(e1);
            const float pB2 = hsum2(e2), pB3 = hsum2(e3);

            // 8 independent MUFUs back-to-back
            const float tA0 = tanhapx(pA0), tA1 = tanhapx(pA1);
            const float tA2 = tanhapx(pA2), tA3 = tanhapx(pA3);
            const float tB0 = tanhapx(pB0), tB1 = tanhapx(pB1);
            const float tB2 = tanhapx(pB2), tB3 = tanhapx(pB3);

            // sig(p) = 0.5*tanh(p/2)+0.5, with p/2 already accumulated
            const float iA = __fmaf_rn(0.5f, tA0, 0.5f);
            const float fA = __fmaf_rn(0.5f, tA1, 0.5f);
            const float oA = __fmaf_rn(0.5f, tA3, 0.5f);
            const float iB = __fmaf_rn(0.5f, tB0, 0.5f);
            const float fB = __fmaf_rn(0.5f, tB1, 0.5f);
            const float oB = __fmaf_rn(0.5f, tB3, 0.5f);

            cA = __fmaf_rn(fA, cA, iA * tA2);
            cB = __fmaf_rn(fB, cB, iB * tB2);
            const float hcA = tanhapx(cA);
            const float hcB = tanhapx(cB);
            if (actA) sh_h[g][nxt][0][jj] = oA * hcA;
            if (actB) sh_h[g][nxt][1][jj] = oB * hcB;
        } else if (out_lane && t > 0) {
            // out[t-1] from the READ buffer, concurrent with gate compute
            const float* hp = &sh_h[g][cur][os][0];
            float y0 = bout, y1 = 0.0f, y2 = 0.0f, y3 = 0.0f;
            #pragma unroll
            for (int kq = 0; kq < 13; kq++) {       // pads are zero in both
                const float4 hv = *reinterpret_cast<const float4*>(hp + kq * 4);
                const float4 wv = *reinterpret_cast<const float4*>(sh_wout + kq * 4);
                y0 = __fmaf_rn(hv.x, wv.x, y0);
                y1 = __fmaf_rn(hv.y, wv.y, y1);
                y2 = __fmaf_rn(hv.z, wv.z, y2);
                y3 = __fmaf_rn(hv.w, wv.w, y3);
            }
            orow[t - 1] = (y0 + y1) + (y2 + y3);
        }

        group_bar(barid);      // only this group's 2 warps
        cur = nxt;
    }

    // tail: out[T-1] from the final h buffer
    if (out_lane) {
        const float* hp = &sh_h[g][cur][os][0];
        float y0 = bout, y1 = 0.0f, y2 = 0.0f, y3 = 0.0f;
        #pragma unroll
        for (int kq = 0; kq < 13; kq++) {
            const float4 hv = *reinterpret_cast<const float4*>(hp + kq * 4);
            const float4 wv = *reinterpret_cast<const float4*>(sh_wout + kq * 4);
            y0 = __fmaf_rn(hv.x, wv.x, y0);
            y1 = __fmaf_rn(hv.y, wv.y, y1);
            y2 = __fmaf_rn(hv.z, wv.z, y2);
            y3 = __fmaf_rn(hv.w, wv.w, y3);
        }
        orow[SEQT - 1] = (y0 + y1) + (y2 + y3);
    }
}

extern "C" void kernel_launch(void* const* d_in, const int* in_sizes, int n_in,
                              void* d_out, int out_size)
{
    const float* x     = (const float*)d_in[0];
    const float* W_ih  = (const float*)d_in[1];
    const float* W_hh  = (const float*)d_in[2];
    const float* b_ih  = (const float*)d_in[3];
    const float* b_hh  = (const float*)d_in[4];
    const float* W_out = (const float*)d_in[5];
    const float* b_out = (const float*)d_in[6];
    float* out = (float*)d_out;

    const int B = in_sizes[0] / SEQT;          // I == 1, x is [B, T, 1]
    const int grid = (B + NB - 1) / NB;
    lstm_fused_kernel<<<grid, BLOCK>>>(x, W_ih, W_hh, b_ih, b_hh, W_out, b_out, out, B);
}